// round 4
// baseline (speedup 1.0000x reference)
#include <cuda_runtime.h>
#include <cstdint>

#define T_    4
#define B_    32
#define C_    384
#define HID_  1536
#define HW_   196
#define NPAIR (B_*HW_)        // 6272 (b,hw) pairs
#define NROW  (NPAIR*T_)      // 25088 rows
#define CW_   (C_/32)         // 12 mask words per row
#define SPIKE_CAP (1u<<22)

#define ON 128                // output-channel chunk
#define NCH (HID_/ON)         // 12
#define CPC 12                // CTAs per chunk (12x12 = 144 = one wave)
#define NTH 768               // threads in fused kernel (24 warps)

#define SMEM_W_BYTES ((C_+1)*ON*4)   // 197120 (row 384 = zeros sentinel)

// ---- static device scratch ----
__device__ float          g_w1t[C_*HID_];
__device__ float          g_w2t[HID_*C_];
__device__ unsigned short g_list[(size_t)NROW*C_];   // per-row active-c lists (padded to mult of 8 with C_)
__device__ int            g_cnt[NROW];
__device__ unsigned       g_spikes[SPIKE_CAP];
__device__ unsigned       g_nspk;
__device__ int            g_pairctr[NCH];

// ---------------- K0: both transposes in one launch + counter reset ----------------
__global__ void k_transpose_both(const float* __restrict__ w1, const float* __restrict__ w2) {
    if (blockIdx.x == 0 && blockIdx.y == 0 && blockIdx.z == 0 && threadIdx.x == 0 && threadIdx.y == 0) {
        g_nspk = 0u;
        #pragma unroll
        for (int i = 0; i < NCH; i++) g_pairctr[i] = 0;
    }
    const float* in; float* outp; int rows, cols;
    if (blockIdx.z == 0) { in = w1; outp = g_w1t; rows = HID_; cols = C_; }
    else                 { in = w2; outp = g_w2t; rows = C_;  cols = HID_; }
    int bx = blockIdx.x * 32, by = blockIdx.y * 32;
    if (bx >= cols || by >= rows) return;

    __shared__ float tile[32][33];
    int x = bx + threadIdx.x;
    #pragma unroll
    for (int k = 0; k < 32; k += 8) {
        int y = by + threadIdx.y + k;
        if (x < cols && y < rows)
            tile[threadIdx.y + k][threadIdx.x] = in[(size_t)y*cols + x];
    }
    __syncthreads();
    int xo = by + threadIdx.x;
    #pragma unroll
    for (int k = 0; k < 32; k += 8) {
        int yo = bx + threadIdx.y + k;
        if (xo < rows && yo < cols)
            outp[(size_t)yo*rows + xo] = tile[threadIdx.x][threadIdx.y + k];
    }
}

// ---------------- K1: fused PLIF1 + list build ----------------
// block = 384 threads = 32 pairs x 12 mask-words; warp w == mask-word w over 32 pairs.
__global__ __launch_bounds__(384)
void k_plif1_list(const float* __restrict__ x, const float* __restrict__ pw1) {
    __shared__ unsigned smask[128][CW_];    // [local row][word]
    const int tid  = threadIdx.x;
    const int p    = tid & 31;              // local pair (lane)
    const int cw   = tid >> 5;              // word index == warp id
    const int pair = blockIdx.x * 32 + p;
    const int b = pair / HW_, hw = pair % HW_;
    const float decay = 1.0f / (1.0f + expf(-pw1[0]));

    unsigned bits[T_] = {0u, 0u, 0u, 0u};
    #pragma unroll 4
    for (int j = 0; j < 32; j++) {
        int c = cw * 32 + j;
        const float* xp = x + ((size_t)b * C_ + c) * HW_ + hw;
        float x0 = __ldg(xp);
        float x1 = __ldg(xp + (size_t)1*B_*C_*HW_);
        float x2 = __ldg(xp + (size_t)2*B_*C_*HW_);
        float x3 = __ldg(xp + (size_t)3*B_*C_*HW_);
        float v = 0.f, h;
        h = v + (x0 - v) * decay; if (h >= 1.0f) { bits[0] |= 1u << j; v = 0.f; } else v = h;
        h = v + (x1 - v) * decay; if (h >= 1.0f) { bits[1] |= 1u << j; v = 0.f; } else v = h;
        h = v + (x2 - v) * decay; if (h >= 1.0f) { bits[2] |= 1u << j; v = 0.f; } else v = h;
        h = v + (x3 - v) * decay; if (h >= 1.0f) { bits[3] |= 1u << j; v = 0.f; } else v = h;
    }
    #pragma unroll
    for (int t = 0; t < T_; t++)
        smask[p * T_ + t][cw] = bits[t];
    __syncthreads();

    // list build: warp cw handles local rows cw, cw+12, ... (<128); lane = p
    const int lane = p;
    for (int r = cw; r < 128; r += CW_) {
        const int grow = blockIdx.x * 128 + r;
        unsigned short* lp = g_list + (size_t)grow * C_;
        int base = 0;
        #pragma unroll
        for (int w = 0; w < CW_; w++) {
            unsigned word = smask[r][w];
            if ((word >> lane) & 1u) {
                int pre = __popc(word & ((1u << lane) - 1u));
                lp[base + pre] = (unsigned short)(w * 32 + lane);
            }
            base += __popc(word);
        }
        // pad to multiple of 8 with sentinel channel C_ (zero weight row)
        int padded = (base + 7) & ~7;
        if (lane < padded - base) lp[base + lane] = (unsigned short)C_;
        if (lane == 0) g_cnt[grow] = base;
    }
}

// ---------------- K2: fused sparse GEMM1 + PLIF2 (persistent, dynamic pairs) ----------------
__device__ __forceinline__ void plif2_comp(float a, float bb, float& v, float decay,
                                           int t, int b, int hw, int o) {
    float xx = a + bb;
    float h = v + (xx - v) * decay;
    if (h >= 1.0f) {
        unsigned pos = atomicAdd(&g_nspk, 1u);
        if (pos < SPIKE_CAP)
            g_spikes[pos] = (unsigned)((((t * B_ + b) * HID_) + o) * HW_ + hw);
        v = 0.f;
    } else {
        v = h;
    }
}

__device__ __forceinline__ void lds_v2u64(unsigned addr, unsigned long long& a,
                                          unsigned long long& b) {
    asm("ld.shared.v2.u64 {%0,%1},[%2];" : "=l"(a), "=l"(b) : "r"(addr));
}
__device__ __forceinline__ void addx2(unsigned long long& a, unsigned long long v) {
    asm("add.rn.f32x2 %0, %0, %1;" : "+l"(a) : "l"(v));
}
__device__ __forceinline__ void acc2(unsigned long long& s01, unsigned long long& s23,
                                     unsigned wbase, unsigned c) {
    unsigned long long va, vb;
    lds_v2u64(wbase + c * 512u, va, vb);
    addx2(s01, va); addx2(s23, vb);
}

__global__ __launch_bounds__(NTH, 1)
void k_gemm1_plif2(const float* __restrict__ pw2, const float* __restrict__ b1) {
    extern __shared__ float ws[];              // [C_+1][ON]
    const int chunk = blockIdx.x;              // 0..NCH-1
    const int tid   = threadIdx.x;
    const int oq    = tid & 31;

    // stage weights once (row C_ = zeros sentinel)
    const float* w1tp = g_w1t + chunk * ON;
    for (int i = tid; i < (C_ + 1) * (ON/4); i += NTH) {
        int c  = i >> 5;
        int o4 = i & 31;
        ((float4*)ws)[i] = (c < C_) ? __ldg((const float4*)(w1tp + (size_t)c * HID_) + o4)
                                    : make_float4(0.f, 0.f, 0.f, 0.f);
    }
    __syncthreads();

    const unsigned wbase = (unsigned)__cvta_generic_to_shared(ws) + oq * 16u;
    const float decay = 1.0f / (1.0f + expf(-pw2[0]));
    const float4 b1v = __ldg((const float4*)(b1 + chunk * ON) + oq);
    const int obase = chunk * ON + oq * 4;

    for (;;) {
        int pair;
        if (oq == 0) pair = atomicAdd(&g_pairctr[chunk], 1);
        pair = __shfl_sync(0xffffffffu, pair, 0);
        if (pair >= NPAIR) break;

        const int row0 = pair * T_;
        const int4 cn = *(const int4*)(g_cnt + row0);    // uniform 16B load

        unsigned long long a01[T_], a23[T_];
        #pragma unroll
        for (int t = 0; t < T_; t++) { a01[t] = 0ull; a23[t] = 0ull; }

        #pragma unroll
        for (int t = 0; t < T_; t++) {
            const int n = (&cn.x)[t];
            const uint4* lp4 = (const uint4*)(g_list + (size_t)(row0 + t) * C_);
            unsigned long long s01 = 0ull, s23 = 0ull;
            const int nc = n < 32 ? n : 32;
            const int trips = (nc + 7) >> 3;             // 0..4, branch-free bodies
            for (int q = 0; q < trips; q++) {
                uint4 L = __ldg(lp4 + q);
                acc2(s01, s23, wbase, L.x & 0xffffu);
                acc2(s01, s23, wbase, L.x >> 16);
                acc2(s01, s23, wbase, L.y & 0xffffu);
                acc2(s01, s23, wbase, L.y >> 16);
                acc2(s01, s23, wbase, L.z & 0xffffu);
                acc2(s01, s23, wbase, L.z >> 16);
                acc2(s01, s23, wbase, L.w & 0xffffu);
                acc2(s01, s23, wbase, L.w >> 16);
            }
            if (n > 32) {                                 // very rare tail, still ascending
                const unsigned short* gp = g_list + (size_t)(row0 + t) * C_;
                for (int j = 32; j < n; j++)
                    acc2(s01, s23, wbase, (unsigned)gp[j]);
            }
            a01[t] = s01; a23[t] = s23;
        }

        // PLIF2 epilogue (exact fp32)
        const int b = pair / HW_, hw = pair % HW_;
        float vx = 0.f, vy = 0.f, vz = 0.f, vw = 0.f;
        #pragma unroll
        for (int t = 0; t < T_; t++) {
            float fx = __uint_as_float((unsigned)(a01[t] & 0xffffffffull));
            float fy = __uint_as_float((unsigned)(a01[t] >> 32));
            float fz = __uint_as_float((unsigned)(a23[t] & 0xffffffffull));
            float fw = __uint_as_float((unsigned)(a23[t] >> 32));
            plif2_comp(fx, b1v.x, vx, decay, t, b, hw, obase + 0);
            plif2_comp(fy, b1v.y, vy, decay, t, b, hw, obase + 1);
            plif2_comp(fz, b1v.z, vz, decay, t, b, hw, obase + 2);
            plif2_comp(fw, b1v.w, vw, decay, t, b, hw, obase + 3);
        }
    }
}

// ---------------- K3: out = b2 ----------------
__global__ void k_outinit(float* __restrict__ out, const float* __restrict__ b2) {
    int i = blockIdx.x * blockDim.x + threadIdx.x;
    const int total4 = T_ * B_ * C_ * HW_ / 4;
    if (i >= total4) return;
    int o = (i / (HW_ / 4)) % C_;
    float bv = __ldg(b2 + o);
    ((float4*)out)[i] = make_float4(bv, bv, bv, bv);
}

// ---------------- K4: scatter spikes ----------------
__global__ void k_scatter(float* __restrict__ out) {
    unsigned n = *(volatile unsigned*)&g_nspk;
    if (n > SPIKE_CAP) n = SPIKE_CAP;
    int wid  = (blockIdx.x * blockDim.x + threadIdx.x) >> 5;
    int lane = threadIdx.x & 31;
    int nw   = (gridDim.x * blockDim.x) >> 5;
    for (unsigned s = wid; s < n; s += nw) {
        unsigned lin = g_spikes[s];
        unsigned hw = lin % HW_;
        unsigned r  = lin / HW_;
        unsigned c  = r % HID_;
        unsigned tb = r / HID_;
        const float* wcol = g_w2t + (size_t)c * C_;
        float* op = out + (size_t)tb * C_ * HW_ + hw;
        for (int o = lane; o < C_; o += 32)
            atomicAdd(op + (size_t)o * HW_, wcol[o]);
    }
}

// ---------------- launch ----------------
extern "C" void kernel_launch(void* const* d_in, const int* in_sizes, int n_in,
                              void* d_out, int out_size) {
    const float* x   = (const float*)d_in[0];
    const float* pw1 = (const float*)d_in[1];
    const float* w1  = (const float*)d_in[2];
    const float* b1  = (const float*)d_in[3];
    const float* pw2 = (const float*)d_in[4];
    const float* w2  = (const float*)d_in[5];
    const float* b2  = (const float*)d_in[6];
    float* out = (float*)d_out;
    (void)in_sizes; (void)n_in; (void)out_size;

    cudaFuncSetAttribute(k_gemm1_plif2,
                         cudaFuncAttributeMaxDynamicSharedMemorySize, SMEM_W_BYTES);

    {   // both transposes + counter reset
        dim3 blk(32, 8), grd(48, 48, 2);
        k_transpose_both<<<grd, blk>>>(w1, w2);
    }

    k_plif1_list<<<NPAIR / 32, 384>>>(x, pw1);

    dim3 g2(NCH, CPC);
    k_gemm1_plif2<<<g2, NTH, SMEM_W_BYTES>>>(pw2, b1);

    k_outinit<<<(T_ * B_ * C_ * HW_ / 4 + 255) / 256, 256>>>(out, b2);
    k_scatter<<<256, 256>>>(out);
}